// round 1
// baseline (speedup 1.0000x reference)
#include <cuda_runtime.h>
#include <cuda_bf16.h>

// Problem constants
#define BB 4
#define LL 1024
#define DD 1024
#define HH 16
#define HD 64
#define MROWS 4096           // B*L
#define PEROWS 2049          // 2*MAX_LEN+1

// Scratch (device globals; allocation is forbidden)
__device__ float g_Q[MROWS * DD];
__device__ float g_K[MROWS * DD];
__device__ float g_V[MROWS * DD];
__device__ float g_O[MROWS * DD];
__device__ float g_S[64 * 1024 * 1024];   // [bh][q][k] attn probs, 256MB

// ---------------------------------------------------------------------------
// NT GEMM: C[M,N] = A[M,K] * B[N,K]^T   (both row-major), M%128==0, N%128==0, K%16==0
// ---------------------------------------------------------------------------
#define GBM 128
#define GBN 128
#define GBK 16
#define GPAD 4   // row stride 132 floats = 528B (multiple of 16B -> float4 safe)

__global__ __launch_bounds__(256, 2)
void gemm_nt(const float* __restrict__ A, const float* __restrict__ B,
             float* __restrict__ C, int M, int N, int K) {
    __shared__ float As[GBK][GBM + GPAD];
    __shared__ float Bs[GBK][GBN + GPAD];
    const int m0 = blockIdx.y * GBM;
    const int n0 = blockIdx.x * GBN;
    const int tid = threadIdx.x;
    const int ty = tid >> 4;          // 0..15, row group (8 rows)
    const int tx = tid & 15;          // 0..15, col group (8 cols)

    float acc[8][8];
#pragma unroll
    for (int i = 0; i < 8; ++i)
#pragma unroll
        for (int j = 0; j < 8; ++j) acc[i][j] = 0.f;

    for (int k0 = 0; k0 < K; k0 += GBK) {
#pragma unroll
        for (int t = 0; t < 2; ++t) {
            int i = tid + t * 256;            // 0..511 float4 slots
            int row = i >> 2;                 // 0..127
            int col = (i & 3) * 4;            // 0,4,8,12
            float4 a = *(const float4*)&A[(size_t)(m0 + row) * K + k0 + col];
            As[col + 0][row] = a.x; As[col + 1][row] = a.y;
            As[col + 2][row] = a.z; As[col + 3][row] = a.w;
            float4 b = *(const float4*)&B[(size_t)(n0 + row) * K + k0 + col];
            Bs[col + 0][row] = b.x; Bs[col + 1][row] = b.y;
            Bs[col + 2][row] = b.z; Bs[col + 3][row] = b.w;
        }
        __syncthreads();
#pragma unroll
        for (int kk = 0; kk < GBK; ++kk) {
            float a[8], b[8];
            float4 a0 = *(float4*)&As[kk][ty * 8];
            float4 a1 = *(float4*)&As[kk][ty * 8 + 4];
            float4 b0 = *(float4*)&Bs[kk][tx * 8];
            float4 b1 = *(float4*)&Bs[kk][tx * 8 + 4];
            a[0]=a0.x; a[1]=a0.y; a[2]=a0.z; a[3]=a0.w;
            a[4]=a1.x; a[5]=a1.y; a[6]=a1.z; a[7]=a1.w;
            b[0]=b0.x; b[1]=b0.y; b[2]=b0.z; b[3]=b0.w;
            b[4]=b1.x; b[5]=b1.y; b[6]=b1.z; b[7]=b1.w;
#pragma unroll
            for (int i = 0; i < 8; ++i)
#pragma unroll
                for (int j = 0; j < 8; ++j)
                    acc[i][j] += a[i] * b[j];
        }
        __syncthreads();
    }
#pragma unroll
    for (int i = 0; i < 8; ++i) {
        size_t r = (size_t)(m0 + ty * 8 + i) * N + n0 + tx * 8;
        *(float4*)&C[r]     = make_float4(acc[i][0], acc[i][1], acc[i][2], acc[i][3]);
        *(float4*)&C[r + 4] = make_float4(acc[i][4], acc[i][5], acc[i][6], acc[i][7]);
    }
}

// ---------------------------------------------------------------------------
// Scores: S[bh,q,k] = (Q.K + Q.pek[k-q+1024]) / 8, causal mask -> -1e30
// 64x64 tiles; only lower-triangular tiles (k0 <= q0). pek window is the
// contiguous 127 rows [k0-q0+961 .. k0-q0+1087].
// ---------------------------------------------------------------------------
#define SC_SMEM_BYTES ((2 * 64 * 68 + 64 * 128) * 4)

__global__ __launch_bounds__(256, 3)
void scores_kernel(const float* __restrict__ pek) {
    const int q0 = blockIdx.y * 64;
    const int k0 = blockIdx.x * 64;
    if (k0 > q0) return;
    extern __shared__ float sm[];
    float* Qs = sm;                 // [64 d][68] transposed
    float* Ks = sm + 64 * 68;       // [64 d][68] transposed
    float* Es = sm + 2 * 64 * 68;   // pek transposed [64 d][128], rows r=0..126

    const int bh = blockIdx.z;
    const int b = bh >> 4, h = bh & 15;
    const int tid = threadIdx.x;

    const float* Qg = g_Q + ((size_t)b * LL) * DD + h * HD;
    const float* Kg = g_K + ((size_t)b * LL) * DD + h * HD;

    for (int i = tid; i < 64 * 64; i += 256) {
        int r = i >> 6, d = i & 63;
        Qs[d * 68 + r] = Qg[(size_t)(q0 + r) * DD + d];
        Ks[d * 68 + r] = Kg[(size_t)(k0 + r) * DD + d];
    }
    const int base0 = k0 - q0 + 1024 - 63;   // >= 1 for all valid tiles
    for (int i = tid; i < 127 * 64; i += 256) {
        int r = i >> 6, d = i & 63;
        Es[d * 128 + r] = pek[(size_t)(base0 + r) * HD + d];
    }
    __syncthreads();

    const int ty = tid >> 4, tx = tid & 15;
    const int qq = ty * 4, kk = tx * 4;
    const int rb = kk - qq + 60;     // row for (i,j): rb + (j - i + 3)

    float acc[4][4];
#pragma unroll
    for (int i = 0; i < 4; ++i)
#pragma unroll
        for (int j = 0; j < 4; ++j) acc[i][j] = 0.f;

#pragma unroll 8
    for (int d = 0; d < 64; ++d) {
        float4 qv = *(float4*)&Qs[d * 68 + qq];
        float4 kv = *(float4*)&Ks[d * 68 + kk];
        float q[4] = {qv.x, qv.y, qv.z, qv.w};
        float k[4] = {kv.x, kv.y, kv.z, kv.w};
        float pv[7];
#pragma unroll
        for (int t = 0; t < 7; ++t) pv[t] = Es[d * 128 + rb + t];
#pragma unroll
        for (int i = 0; i < 4; ++i)
#pragma unroll
            for (int j = 0; j < 4; ++j)
                acc[i][j] += q[i] * (k[j] + pv[j - i + 3]);
    }

    float* Sg = g_S + ((size_t)bh << 20);
#pragma unroll
    for (int i = 0; i < 4; ++i) {
        int qg = q0 + qq + i;
#pragma unroll
        for (int j = 0; j < 4; ++j) {
            int kg = k0 + kk + j;
            float v = acc[i][j] * 0.125f;
            if (kg > qg) v = -1e30f;
            Sg[(size_t)qg * 1024 + kg] = v;
        }
    }
}

// ---------------------------------------------------------------------------
// Row softmax with causal mask; writes 0 above diagonal.
// One block (256 thr) per row of 1024.
// ---------------------------------------------------------------------------
__global__ __launch_bounds__(256)
void softmax_kernel() {
    const int row = blockIdx.x;             // bh*1024 + q
    const int q = row & 1023;
    float* Sr = g_S + (size_t)row * 1024;
    const int tid = threadIdx.x;

    float v[4];
    float mx = -1e30f;
#pragma unroll
    for (int t = 0; t < 4; ++t) {
        int k = tid + t * 256;
        v[t] = (k <= q) ? Sr[k] : -1e30f;
        mx = fmaxf(mx, v[t]);
    }
    __shared__ float red[8];
#pragma unroll
    for (int o = 16; o; o >>= 1) mx = fmaxf(mx, __shfl_xor_sync(0xffffffffu, mx, o));
    if ((tid & 31) == 0) red[tid >> 5] = mx;
    __syncthreads();
    float m = red[0];
#pragma unroll
    for (int i = 1; i < 8; ++i) m = fmaxf(m, red[i]);
    __syncthreads();

    float s = 0.f;
#pragma unroll
    for (int t = 0; t < 4; ++t) {
        int k = tid + t * 256;
        v[t] = (k <= q) ? expf(v[t] - m) : 0.f;
        s += v[t];
    }
#pragma unroll
    for (int o = 16; o; o >>= 1) s += __shfl_xor_sync(0xffffffffu, s, o);
    if ((tid & 31) == 0) red[tid >> 5] = s;
    __syncthreads();
    float tot = 0.f;
#pragma unroll
    for (int i = 0; i < 8; ++i) tot += red[i];
    float inv = 1.f / tot;
#pragma unroll
    for (int t = 0; t < 4; ++t) {
        int k = tid + t * 256;
        Sr[k] = v[t] * inv;
    }
}

// ---------------------------------------------------------------------------
// Output: O[bh,q,d] = sum_{k<=q} P[q,k] * (V[k,d] + pev[k-q+1024,d])
// Per (bh, q-tile) block loops over lower-triangular k-tiles.
// ---------------------------------------------------------------------------
#define OUT_SMEM_BYTES ((64 * 65 + 64 * 68 + 127 * 68) * 4)

__global__ __launch_bounds__(256, 3)
void out_kernel(const float* __restrict__ pev) {
    extern __shared__ float sm[];
    float* Ps = sm;                       // [64 q][65 k]
    float* Vs = sm + 64 * 65;             // [64 k][68 d]
    float* Es = sm + 64 * 65 + 64 * 68;   // pev rows [127][68 d]

    const int q0 = blockIdx.x * 64;
    const int bh = blockIdx.y;
    const int b = bh >> 4, h = bh & 15;
    const int tid = threadIdx.x;
    const int ty = tid >> 4, tx = tid & 15;
    const int qq = ty * 4, dd = tx * 4;

    const float* Pg = g_S + ((size_t)bh << 20);
    const float* Vg = g_V + ((size_t)b * LL) * DD + h * HD;

    float acc[4][4];
#pragma unroll
    for (int i = 0; i < 4; ++i)
#pragma unroll
        for (int j = 0; j < 4; ++j) acc[i][j] = 0.f;

    for (int k0 = 0; k0 <= q0; k0 += 64) {
        for (int i = tid; i < 64 * 64; i += 256) {
            int r = i >> 6, c = i & 63;
            Ps[r * 65 + c] = Pg[(size_t)(q0 + r) * 1024 + k0 + c];
            Vs[r * 68 + c] = Vg[(size_t)(k0 + r) * DD + c];
        }
        const int base0 = k0 - q0 + 1024 - 63;
        for (int i = tid; i < 127 * 64; i += 256) {
            int r = i >> 6, c = i & 63;
            Es[r * 68 + c] = pev[(size_t)(base0 + r) * HD + c];
        }
        __syncthreads();

#pragma unroll 4
        for (int kk = 0; kk < 64; ++kk) {
            float4 v = *(float4*)&Vs[kk * 68 + dd];
#pragma unroll
            for (int i = 0; i < 4; ++i) {
                float p = Ps[(qq + i) * 65 + kk];
                int r = kk - qq - i + 63;          // 0..126
                float4 e = *(float4*)&Es[r * 68 + dd];
                acc[i][0] += p * (v.x + e.x);
                acc[i][1] += p * (v.y + e.y);
                acc[i][2] += p * (v.z + e.z);
                acc[i][3] += p * (v.w + e.w);
            }
        }
        __syncthreads();
    }

    float* Og = g_O + ((size_t)b * LL + q0) * DD + h * HD;
#pragma unroll
    for (int i = 0; i < 4; ++i)
        *(float4*)&Og[(size_t)(qq + i) * DD + dd] =
            make_float4(acc[i][0], acc[i][1], acc[i][2], acc[i][3]);
}

// ---------------------------------------------------------------------------
// Launch
// ---------------------------------------------------------------------------
extern "C" void kernel_launch(void* const* d_in, const int* in_sizes, int n_in,
                              void* d_out, int out_size) {
    const float* x   = (const float*)d_in[0];
    const float* Wq  = (const float*)d_in[1];
    const float* Wk  = (const float*)d_in[2];
    const float* Wv  = (const float*)d_in[3];
    const float* Wo  = (const float*)d_in[4];
    const float* pek = (const float*)d_in[5];
    const float* pev = (const float*)d_in[6];
    float* out = (float*)d_out;

    float *Q, *K, *V, *O;
    cudaGetSymbolAddress((void**)&Q, g_Q);
    cudaGetSymbolAddress((void**)&K, g_K);
    cudaGetSymbolAddress((void**)&V, g_V);
    cudaGetSymbolAddress((void**)&O, g_O);

    cudaFuncSetAttribute(scores_kernel, cudaFuncAttributeMaxDynamicSharedMemorySize, SC_SMEM_BYTES);
    cudaFuncSetAttribute(out_kernel,    cudaFuncAttributeMaxDynamicSharedMemorySize, OUT_SMEM_BYTES);

    dim3 gproj(DD / GBN, MROWS / GBM);   // (8, 32)

    gemm_nt<<<gproj, 256>>>(x, Wq, Q, MROWS, DD, DD);
    gemm_nt<<<gproj, 256>>>(x, Wk, K, MROWS, DD, DD);
    gemm_nt<<<gproj, 256>>>(x, Wv, V, MROWS, DD, DD);

    scores_kernel<<<dim3(16, 16, 64), 256, SC_SMEM_BYTES>>>(pek);
    softmax_kernel<<<64 * 1024, 256>>>();
    out_kernel<<<dim3(16, 64), 256, OUT_SMEM_BYTES>>>(pev);

    gemm_nt<<<gproj, 256>>>(O, Wo, out, MROWS, DD, DD);
}

// round 3
// speedup vs baseline: 1.3219x; 1.3219x over previous
#include <cuda_runtime.h>
#include <cuda_bf16.h>
#include <cstdint>

// Problem constants
#define BB 4
#define LL 1024
#define DD 1024
#define HH 16
#define HD 64
#define MROWS 4096           // B*L

// Scratch (device globals; allocation is forbidden)
__device__ float g_Q[MROWS * DD];
__device__ float g_K[MROWS * DD];
__device__ float g_V[MROWS * DD];
__device__ float g_O[MROWS * DD];
__device__ float g_S[64 * 1024 * 1024];   // [bh][q][k] attn probs, 256MB
__device__ __nv_bfloat16 g_xh[MROWS * DD];
__device__ __nv_bfloat16 g_xl[MROWS * DD];
__device__ __nv_bfloat16 g_wh[DD * DD];
__device__ __nv_bfloat16 g_wl[DD * DD];

__device__ __forceinline__ uint32_t smem_u32(const void* p) {
    uint32_t a;
    asm("{ .reg .u64 t; cvta.to.shared.u64 t, %1; cvt.u32.u64 %0, t; }" : "=r"(a) : "l"(p));
    return a;
}

// ---------------------------------------------------------------------------
// fp32 -> bf16 hi/lo split
// ---------------------------------------------------------------------------
__global__ __launch_bounds__(256)
void split_kernel(const float* __restrict__ s, __nv_bfloat16* __restrict__ h,
                  __nv_bfloat16* __restrict__ l, int n4) {
    int i = blockIdx.x * 256 + threadIdx.x;
    if (i >= n4) return;
    float4 v = ((const float4*)s)[i];
    __nv_bfloat16 h0 = __float2bfloat16(v.x);
    __nv_bfloat16 h1 = __float2bfloat16(v.y);
    __nv_bfloat16 h2 = __float2bfloat16(v.z);
    __nv_bfloat16 h3 = __float2bfloat16(v.w);
    __nv_bfloat16 l0 = __float2bfloat16(v.x - __bfloat162float(h0));
    __nv_bfloat16 l1 = __float2bfloat16(v.y - __bfloat162float(h1));
    __nv_bfloat16 l2 = __float2bfloat16(v.z - __bfloat162float(h2));
    __nv_bfloat16 l3 = __float2bfloat16(v.w - __bfloat162float(h3));
    __nv_bfloat162 hh0 = __nv_bfloat162(h0, h1), hh1 = __nv_bfloat162(h2, h3);
    __nv_bfloat162 ll0 = __nv_bfloat162(l0, l1), ll1 = __nv_bfloat162(l2, l3);
    ((uint2*)h)[i] = make_uint2(*(uint32_t*)&hh0, *(uint32_t*)&hh1);
    ((uint2*)l)[i] = make_uint2(*(uint32_t*)&ll0, *(uint32_t*)&ll1);
}

// ---------------------------------------------------------------------------
// mma.sync bf16x3 GEMM: C[M,1024] = A[M,1024] * B[1024,1024]^T
// C = Ah*Bh + Ah*Bl + Al*Bh (fp32 accum). 128x128 CTA tile, 8 warps (64x32),
// k-chunk 32, double-buffered cp.async, padded smem rows (80B) for ldmatrix.
// ---------------------------------------------------------------------------
#define GKDIM 1024
#define NIT 32                       // 1024/32
#define TILE_B 10240                 // 128 rows * 80 bytes
#define STAGE_B (4 * TILE_B)         // Ah, Al, Bh, Bl
#define GEMM_SMEM (2 * STAGE_B)      // 81920 B

#define MMA_OP(c, af, bf) \
    asm volatile("mma.sync.aligned.m16n8k16.row.col.f32.bf16.bf16.f32 " \
                 "{%0,%1,%2,%3}, {%4,%5,%6,%7}, {%8,%9}, {%0,%1,%2,%3};" \
                 : "+f"((c)[0]), "+f"((c)[1]), "+f"((c)[2]), "+f"((c)[3]) \
                 : "r"((af)[0]), "r"((af)[1]), "r"((af)[2]), "r"((af)[3]), \
                   "r"((bf)[0]), "r"((bf)[1]))

__global__ __launch_bounds__(256, 1)
void gemm_mma(const __nv_bfloat16* __restrict__ Ah, const __nv_bfloat16* __restrict__ Al,
              const __nv_bfloat16* __restrict__ Bh, const __nv_bfloat16* __restrict__ Bl,
              float* __restrict__ C) {
    extern __shared__ __align__(128) char sm[];
    const uint32_t smb = smem_u32(sm);
    const int tid = threadIdx.x;
    const int wid = tid >> 5, lane = tid & 31;
    const int m0 = blockIdx.y * 128, n0 = blockIdx.x * 128;
    const int wm = wid & 1, wn = wid >> 1;       // 2 x 4 warp grid

    const __nv_bfloat16* srcs[4] = {
        Ah + (size_t)m0 * GKDIM, Al + (size_t)m0 * GKDIM,
        Bh + (size_t)n0 * GKDIM, Bl + (size_t)n0 * GKDIM };

    auto stage_load = [&](int kc, int s) {
#pragma unroll
        for (int rep = 0; rep < 8; ++rep) {
            int idx = tid + rep * 256;           // 0..2047
            int tile = idx >> 9;                 // 0..3
            int r = (idx >> 2) & 127;            // row in tile
            int c = idx & 3;                     // 16B chunk in row
            const void* gp = srcs[tile] + (size_t)r * GKDIM + kc * 32 + c * 8;
            uint32_t dp = smb + s * STAGE_B + tile * TILE_B + r * 80 + c * 16;
            asm volatile("cp.async.cg.shared.global [%0], [%1], 16;" :: "r"(dp), "l"(gp));
        }
        asm volatile("cp.async.commit_group;");
    };

    float acc[4][4][4];
#pragma unroll
    for (int i = 0; i < 4; ++i)
#pragma unroll
        for (int j = 0; j < 4; ++j)
#pragma unroll
            for (int k = 0; k < 4; ++k) acc[i][j][k] = 0.f;

    stage_load(0, 0);

    for (int it = 0; it < NIT; ++it) {
        if (it + 1 < NIT) {
            stage_load(it + 1, (it + 1) & 1);
            asm volatile("cp.async.wait_group 1;");
        } else {
            asm volatile("cp.async.wait_group 0;");
        }
        __syncthreads();

        const uint32_t base = smb + (it & 1) * STAGE_B;
        const uint32_t aHb = base, aLb = base + TILE_B;
        const uint32_t bHb = base + 2 * TILE_B, bLb = base + 3 * TILE_B;
        const int arow = wm * 64 + (lane & 15);
        const int acolb = (lane & 16) >> 1;          // 0 or 8
        const int brow = wn * 32 + (lane & 7);
        const int bcolb = lane & 8;                  // 0 or 8

#pragma unroll
        for (int k16 = 0; k16 < 32; k16 += 16) {
            uint32_t ah[4][4], al[4][4], bh[4][2], bl[4][2];
#pragma unroll
            for (int mi = 0; mi < 4; ++mi) {
                uint32_t ad = aHb + ((arow + mi * 16) * 40 + k16 + acolb) * 2;
                asm volatile("ldmatrix.sync.aligned.m8n8.x4.shared.b16 {%0,%1,%2,%3}, [%4];"
                             : "=r"(ah[mi][0]), "=r"(ah[mi][1]), "=r"(ah[mi][2]), "=r"(ah[mi][3])
                             : "r"(ad));
                uint32_t ad2 = aLb + ((arow + mi * 16) * 40 + k16 + acolb) * 2;
                asm volatile("ldmatrix.sync.aligned.m8n8.x4.shared.b16 {%0,%1,%2,%3}, [%4];"
                             : "=r"(al[mi][0]), "=r"(al[mi][1]), "=r"(al[mi][2]), "=r"(al[mi][3])
                             : "r"(ad2));
            }
#pragma unroll
            for (int ni = 0; ni < 4; ++ni) {
                uint32_t bd = bHb + ((brow + ni * 8) * 40 + k16 + bcolb) * 2;
                asm volatile("ldmatrix.sync.aligned.m8n8.x2.shared.b16 {%0,%1}, [%2];"
                             : "=r"(bh[ni][0]), "=r"(bh[ni][1]) : "r"(bd));
                uint32_t bd2 = bLb + ((brow + ni * 8) * 40 + k16 + bcolb) * 2;
                asm volatile("ldmatrix.sync.aligned.m8n8.x2.shared.b16 {%0,%1}, [%2];"
                             : "=r"(bl[ni][0]), "=r"(bl[ni][1]) : "r"(bd2));
            }
#pragma unroll
            for (int mi = 0; mi < 4; ++mi)
#pragma unroll
                for (int ni = 0; ni < 4; ++ni) {
                    MMA_OP(acc[mi][ni], ah[mi], bh[ni]);
                    MMA_OP(acc[mi][ni], ah[mi], bl[ni]);
                    MMA_OP(acc[mi][ni], al[mi], bh[ni]);
                }
        }
        __syncthreads();
    }

    // epilogue: c0,c1 -> (row, col), (row, col+1); c2,c3 -> (row+8, ...)
    const int crow = m0 + wm * 64 + (lane >> 2);
    const int ccol = n0 + wn * 32 + (lane & 3) * 2;
#pragma unroll
    for (int mi = 0; mi < 4; ++mi)
#pragma unroll
        for (int ni = 0; ni < 4; ++ni) {
            size_t r0 = (size_t)(crow + mi * 16) * DD + ccol + ni * 8;
            size_t r1 = (size_t)(crow + mi * 16 + 8) * DD + ccol + ni * 8;
            *(float2*)&C[r0] = make_float2(acc[mi][ni][0], acc[mi][ni][1]);
            *(float2*)&C[r1] = make_float2(acc[mi][ni][2], acc[mi][ni][3]);
        }
}

// ---------------------------------------------------------------------------
// Scores: S[bh,q,k] = (Q.K + Q.pek[k-q+1024]) / 8, causal mask -> -1e30
// ---------------------------------------------------------------------------
#define SC_SMEM_BYTES ((2 * 64 * 68 + 64 * 128) * 4)

__global__ __launch_bounds__(256, 3)
void scores_kernel(const float* __restrict__ pek) {
    const int q0 = blockIdx.y * 64;
    const int k0 = blockIdx.x * 64;
    if (k0 > q0) return;
    extern __shared__ float smf[];
    float* Qs = smf;
    float* Ks = smf + 64 * 68;
    float* Es = smf + 2 * 64 * 68;

    const int bh = blockIdx.z;
    const int b = bh >> 4, h = bh & 15;
    const int tid = threadIdx.x;

    const float* Qg = g_Q + ((size_t)b * LL) * DD + h * HD;
    const float* Kg = g_K + ((size_t)b * LL) * DD + h * HD;

    for (int i = tid; i < 64 * 64; i += 256) {
        int r = i >> 6, d = i & 63;
        Qs[d * 68 + r] = Qg[(size_t)(q0 + r) * DD + d];
        Ks[d * 68 + r] = Kg[(size_t)(k0 + r) * DD + d];
    }
    const int base0 = k0 - q0 + 1024 - 63;
    for (int i = tid; i < 127 * 64; i += 256) {
        int r = i >> 6, d = i & 63;
        Es[d * 128 + r] = pek[(size_t)(base0 + r) * HD + d];
    }
    __syncthreads();

    const int ty = tid >> 4, tx = tid & 15;
    const int qq = ty * 4, kk = tx * 4;
    const int rb = kk - qq + 60;

    float acc[4][4];
#pragma unroll
    for (int i = 0; i < 4; ++i)
#pragma unroll
        for (int j = 0; j < 4; ++j) acc[i][j] = 0.f;

#pragma unroll 8
    for (int d = 0; d < 64; ++d) {
        float4 qv = *(float4*)&Qs[d * 68 + qq];
        float4 kv = *(float4*)&Ks[d * 68 + kk];
        float q[4] = {qv.x, qv.y, qv.z, qv.w};
        float k[4] = {kv.x, kv.y, kv.z, kv.w};
        float pv[7];
#pragma unroll
        for (int t = 0; t < 7; ++t) pv[t] = Es[d * 128 + rb + t];
#pragma unroll
        for (int i = 0; i < 4; ++i)
#pragma unroll
            for (int j = 0; j < 4; ++j)
                acc[i][j] += q[i] * (k[j] + pv[j - i + 3]);
    }

    float* Sg = g_S + ((size_t)bh << 20);
#pragma unroll
    for (int i = 0; i < 4; ++i) {
        int qg = q0 + qq + i;
#pragma unroll
        for (int j = 0; j < 4; ++j) {
            int kg = k0 + kk + j;
            float v = acc[i][j] * 0.125f;
            if (kg > qg) v = -1e30f;
            Sg[(size_t)qg * 1024 + kg] = v;
        }
    }
}

// ---------------------------------------------------------------------------
// Row softmax with causal mask
// ---------------------------------------------------------------------------
__global__ __launch_bounds__(256)
void softmax_kernel() {
    const int row = blockIdx.x;
    const int q = row & 1023;
    float* Sr = g_S + (size_t)row * 1024;
    const int tid = threadIdx.x;

    float v[4];
    float mx = -1e30f;
#pragma unroll
    for (int t = 0; t < 4; ++t) {
        int k = tid + t * 256;
        v[t] = (k <= q) ? Sr[k] : -1e30f;
        mx = fmaxf(mx, v[t]);
    }
    __shared__ float red[8];
#pragma unroll
    for (int o = 16; o; o >>= 1) mx = fmaxf(mx, __shfl_xor_sync(0xffffffffu, mx, o));
    if ((tid & 31) == 0) red[tid >> 5] = mx;
    __syncthreads();
    float m = red[0];
#pragma unroll
    for (int i = 1; i < 8; ++i) m = fmaxf(m, red[i]);
    __syncthreads();

    float s = 0.f;
#pragma unroll
    for (int t = 0; t < 4; ++t) {
        int k = tid + t * 256;
        v[t] = (k <= q) ? expf(v[t] - m) : 0.f;
        s += v[t];
    }
#pragma unroll
    for (int o = 16; o; o >>= 1) s += __shfl_xor_sync(0xffffffffu, s, o);
    if ((tid & 31) == 0) red[tid >> 5] = s;
    __syncthreads();
    float tot = 0.f;
#pragma unroll
    for (int i = 0; i < 8; ++i) tot += red[i];
    float inv = 1.f / tot;
#pragma unroll
    for (int t = 0; t < 4; ++t) {
        int k = tid + t * 256;
        Sr[k] = v[t] * inv;
    }
}

// ---------------------------------------------------------------------------
// Output: O[bh,q,d] = sum_{k<=q} P[q,k] * (V[k,d] + pev[k-q+1024,d])
// ---------------------------------------------------------------------------
#define OUT_SMEM_BYTES ((64 * 65 + 64 * 68 + 127 * 68) * 4)

__global__ __launch_bounds__(256, 3)
void out_kernel(const float* __restrict__ pev) {
    extern __shared__ float smf[];
    float* Ps = smf;
    float* Vs = smf + 64 * 65;
    float* Es = smf + 64 * 65 + 64 * 68;

    const int q0 = blockIdx.x * 64;
    const int bh = blockIdx.y;
    const int b = bh >> 4, h = bh & 15;
    const int tid = threadIdx.x;
    const int ty = tid >> 4, tx = tid & 15;
    const int qq = ty * 4, dd = tx * 4;

    const float* Pg = g_S + ((size_t)bh << 20);
    const float* Vg = g_V + ((size_t)b * LL) * DD + h * HD;

    float acc[4][4];
#pragma unroll
    for (int i = 0; i < 4; ++i)
#pragma unroll
        for (int j = 0; j < 4; ++j) acc[i][j] = 0.f;

    for (int k0 = 0; k0 <= q0; k0 += 64) {
        for (int i = tid; i < 64 * 64; i += 256) {
            int r = i >> 6, c = i & 63;
            Ps[r * 65 + c] = Pg[(size_t)(q0 + r) * 1024 + k0 + c];
            Vs[r * 68 + c] = Vg[(size_t)(k0 + r) * DD + c];
        }
        const int base0 = k0 - q0 + 1024 - 63;
        for (int i = tid; i < 127 * 64; i += 256) {
            int r = i >> 6, c = i & 63;
            Es[r * 68 + c] = pev[(size_t)(base0 + r) * HD + c];
        }
        __syncthreads();

#pragma unroll 4
        for (int kk = 0; kk < 64; ++kk) {
            float4 v = *(float4*)&Vs[kk * 68 + dd];
#pragma unroll
            for (int i = 0; i < 4; ++i) {
                float p = Ps[(qq + i) * 65 + kk];
                int r = kk - qq - i + 63;
                float4 e = *(float4*)&Es[r * 68 + dd];
                acc[i][0] += p * (v.x + e.x);
                acc[i][1] += p * (v.y + e.y);
                acc[i][2] += p * (v.z + e.z);
                acc[i][3] += p * (v.w + e.w);
            }
        }
        __syncthreads();
    }

    float* Og = g_O + ((size_t)b * LL + q0) * DD + h * HD;
#pragma unroll
    for (int i = 0; i < 4; ++i)
        *(float4*)&Og[(size_t)(qq + i) * DD + dd] =
            make_float4(acc[i][0], acc[i][1], acc[i][2], acc[i][3]);
}

// ---------------------------------------------------------------------------
// Launch
// ---------------------------------------------------------------------------
extern "C" void kernel_launch(void* const* d_in, const int* in_sizes, int n_in,
                              void* d_out, int out_size) {
    const float* x   = (const float*)d_in[0];
    const float* Wq  = (const float*)d_in[1];
    const float* Wk  = (const float*)d_in[2];
    const float* Wv  = (const float*)d_in[3];
    const float* Wo  = (const float*)d_in[4];
    const float* pek = (const float*)d_in[5];
    const float* pev = (const float*)d_in[6];
    float* out = (float*)d_out;

    float *Q, *K, *V, *O;
    __nv_bfloat16 *xh, *xl, *wh, *wl;
    cudaGetSymbolAddress((void**)&Q, g_Q);
    cudaGetSymbolAddress((void**)&K, g_K);
    cudaGetSymbolAddress((void**)&V, g_V);
    cudaGetSymbolAddress((void**)&O, g_O);
    cudaGetSymbolAddress((void**)&xh, g_xh);
    cudaGetSymbolAddress((void**)&xl, g_xl);
    cudaGetSymbolAddress((void**)&wh, g_wh);
    cudaGetSymbolAddress((void**)&wl, g_wl);

    cudaFuncSetAttribute(gemm_mma, cudaFuncAttributeMaxDynamicSharedMemorySize, GEMM_SMEM);
    cudaFuncSetAttribute(scores_kernel, cudaFuncAttributeMaxDynamicSharedMemorySize, SC_SMEM_BYTES);
    cudaFuncSetAttribute(out_kernel,    cudaFuncAttributeMaxDynamicSharedMemorySize, OUT_SMEM_BYTES);

    const int n4x = MROWS * DD / 4;      // 1,048,576
    const int n4w = DD * DD / 4;         // 262,144
    dim3 ggemm(DD / 128, MROWS / 128);   // (8, 32)

    split_kernel<<<(n4x + 255) / 256, 256>>>(x, xh, xl, n4x);

    split_kernel<<<(n4w + 255) / 256, 256>>>(Wq, wh, wl, n4w);
    gemm_mma<<<ggemm, 256, GEMM_SMEM>>>(xh, xl, wh, wl, Q);
    split_kernel<<<(n4w + 255) / 256, 256>>>(Wk, wh, wl, n4w);
    gemm_mma<<<ggemm, 256, GEMM_SMEM>>>(xh, xl, wh, wl, K);
    split_kernel<<<(n4w + 255) / 256, 256>>>(Wv, wh, wl, n4w);
    gemm_mma<<<ggemm, 256, GEMM_SMEM>>>(xh, xl, wh, wl, V);

    scores_kernel<<<dim3(16, 16, 64), 256, SC_SMEM_BYTES>>>(pek);
    softmax_kernel<<<64 * 1024, 256>>>();
    out_kernel<<<dim3(16, 64), 256, OUT_SMEM_BYTES>>>(pev);

    split_kernel<<<(n4x + 255) / 256, 256>>>(O, xh, xl, n4x);
    split_kernel<<<(n4w + 255) / 256, 256>>>(Wo, wh, wl, n4w);
    gemm_mma<<<ggemm, 256, GEMM_SMEM>>>(xh, xl, wh, wl, out);
}

// round 4
// speedup vs baseline: 1.9714x; 1.4914x over previous
#include <cuda_runtime.h>
#include <cuda_bf16.h>
#include <cstdint>

// Problem constants
#define BB 4
#define LL 1024
#define DD 1024
#define HH 16
#define HD 64
#define MROWS 4096           // B*L
#define PEN 2049

// Scratch (device globals; allocation is forbidden)
__device__ float g_Q[MROWS * DD];
__device__ float g_K[MROWS * DD];
__device__ float g_V[MROWS * DD];
__device__ float g_O[MROWS * DD];
__device__ float g_S[64 * 1024 * 1024];   // [bh][q][k] attn probs, 256MB
__device__ __nv_bfloat16 g_xh[MROWS * DD];
__device__ __nv_bfloat16 g_xl[MROWS * DD];
__device__ __nv_bfloat16 g_wh[DD * DD];
__device__ __nv_bfloat16 g_wl[DD * DD];
__device__ __nv_bfloat16 g_Qh[MROWS * DD];
__device__ __nv_bfloat16 g_Ql[MROWS * DD];
__device__ __nv_bfloat16 g_Kh[MROWS * DD];
__device__ __nv_bfloat16 g_Kl[MROWS * DD];
__device__ __nv_bfloat16 g_Vh[MROWS * DD];
__device__ __nv_bfloat16 g_Vl[MROWS * DD];
__device__ __nv_bfloat16 g_pekh[PEN * HD];
__device__ __nv_bfloat16 g_pekl[PEN * HD];
__device__ __nv_bfloat16 g_pevh[PEN * HD];
__device__ __nv_bfloat16 g_pevl[PEN * HD];

__device__ __forceinline__ uint32_t smem_u32(const void* p) {
    uint32_t a;
    asm("{ .reg .u64 t; cvta.to.shared.u64 t, %1; cvt.u32.u64 %0, t; }" : "=r"(a) : "l"(p));
    return a;
}

#define MMA_OP(c, af, bf) \
    asm volatile("mma.sync.aligned.m16n8k16.row.col.f32.bf16.bf16.f32 " \
                 "{%0,%1,%2,%3}, {%4,%5,%6,%7}, {%8,%9}, {%0,%1,%2,%3};" \
                 : "+f"((c)[0]), "+f"((c)[1]), "+f"((c)[2]), "+f"((c)[3]) \
                 : "r"((af)[0]), "r"((af)[1]), "r"((af)[2]), "r"((af)[3]), \
                   "r"((bf)[0]), "r"((bf)[1]))

#define LDSM4(d0,d1,d2,d3,a) \
    asm volatile("ldmatrix.sync.aligned.m8n8.x4.shared.b16 {%0,%1,%2,%3}, [%4];" \
                 : "=r"(d0), "=r"(d1), "=r"(d2), "=r"(d3) : "r"(a))
#define LDSM4T(d0,d1,d2,d3,a) \
    asm volatile("ldmatrix.sync.aligned.m8n8.x4.trans.shared.b16 {%0,%1,%2,%3}, [%4];" \
                 : "=r"(d0), "=r"(d1), "=r"(d2), "=r"(d3) : "r"(a))

__device__ __forceinline__ uint16_t bf16bits(__nv_bfloat16 h) {
    return *reinterpret_cast<uint16_t*>(&h);
}
__device__ __forceinline__ uint32_t pack2(__nv_bfloat16 a, __nv_bfloat16 b) {
    __nv_bfloat162 t(a, b);
    return *reinterpret_cast<uint32_t*>(&t);
}

// ---------------------------------------------------------------------------
// fp32 -> bf16 hi/lo split
// ---------------------------------------------------------------------------
__global__ __launch_bounds__(256)
void split_kernel(const float* __restrict__ s, __nv_bfloat16* __restrict__ h,
                  __nv_bfloat16* __restrict__ l, int n4) {
    int i = blockIdx.x * 256 + threadIdx.x;
    if (i >= n4) return;
    float4 v = ((const float4*)s)[i];
    __nv_bfloat16 h0 = __float2bfloat16(v.x);
    __nv_bfloat16 h1 = __float2bfloat16(v.y);
    __nv_bfloat16 h2 = __float2bfloat16(v.z);
    __nv_bfloat16 h3 = __float2bfloat16(v.w);
    __nv_bfloat16 l0 = __float2bfloat16(v.x - __bfloat162float(h0));
    __nv_bfloat16 l1 = __float2bfloat16(v.y - __bfloat162float(h1));
    __nv_bfloat16 l2 = __float2bfloat16(v.z - __bfloat162float(h2));
    __nv_bfloat16 l3 = __float2bfloat16(v.w - __bfloat162float(h3));
    ((uint2*)h)[i] = make_uint2(pack2(h0, h1), pack2(h2, h3));
    ((uint2*)l)[i] = make_uint2(pack2(l0, l1), pack2(l2, l3));
}

// ---------------------------------------------------------------------------
// mma.sync bf16x3 GEMM: C[M,1024] = A[M,1024] * B[1024,1024]^T  (unchanged)
// ---------------------------------------------------------------------------
#define GKDIM 1024
#define NIT 32
#define TILE_B 10240
#define STAGE_B (4 * TILE_B)
#define GEMM_SMEM (2 * STAGE_B)

__global__ __launch_bounds__(256, 1)
void gemm_mma(const __nv_bfloat16* __restrict__ Ah, const __nv_bfloat16* __restrict__ Al,
              const __nv_bfloat16* __restrict__ Bh, const __nv_bfloat16* __restrict__ Bl,
              float* __restrict__ C) {
    extern __shared__ __align__(128) char sm[];
    const uint32_t smb = smem_u32(sm);
    const int tid = threadIdx.x;
    const int wid = tid >> 5, lane = tid & 31;
    const int m0 = blockIdx.y * 128, n0 = blockIdx.x * 128;
    const int wm = wid & 1, wn = wid >> 1;

    const __nv_bfloat16* srcs[4] = {
        Ah + (size_t)m0 * GKDIM, Al + (size_t)m0 * GKDIM,
        Bh + (size_t)n0 * GKDIM, Bl + (size_t)n0 * GKDIM };

    auto stage_load = [&](int kc, int s) {
#pragma unroll
        for (int rep = 0; rep < 8; ++rep) {
            int idx = tid + rep * 256;
            int tile = idx >> 9;
            int r = (idx >> 2) & 127;
            int c = idx & 3;
            const void* gp = srcs[tile] + (size_t)r * GKDIM + kc * 32 + c * 8;
            uint32_t dp = smb + s * STAGE_B + tile * TILE_B + r * 80 + c * 16;
            asm volatile("cp.async.cg.shared.global [%0], [%1], 16;" :: "r"(dp), "l"(gp));
        }
        asm volatile("cp.async.commit_group;");
    };

    float acc[4][4][4];
#pragma unroll
    for (int i = 0; i < 4; ++i)
#pragma unroll
        for (int j = 0; j < 4; ++j)
#pragma unroll
            for (int k = 0; k < 4; ++k) acc[i][j][k] = 0.f;

    stage_load(0, 0);

    for (int it = 0; it < NIT; ++it) {
        if (it + 1 < NIT) {
            stage_load(it + 1, (it + 1) & 1);
            asm volatile("cp.async.wait_group 1;");
        } else {
            asm volatile("cp.async.wait_group 0;");
        }
        __syncthreads();

        const uint32_t base = smb + (it & 1) * STAGE_B;
        const uint32_t aHb = base, aLb = base + TILE_B;
        const uint32_t bHb = base + 2 * TILE_B, bLb = base + 3 * TILE_B;
        const int arow = wm * 64 + (lane & 15);
        const int acolb = (lane & 16) >> 1;
        const int brow = wn * 32 + (lane & 7);
        const int bcolb = lane & 8;

#pragma unroll
        for (int k16 = 0; k16 < 32; k16 += 16) {
            uint32_t ah[4][4], al[4][4], bh[4][2], bl[4][2];
#pragma unroll
            for (int mi = 0; mi < 4; ++mi) {
                uint32_t ad = aHb + ((arow + mi * 16) * 40 + k16 + acolb) * 2;
                LDSM4(ah[mi][0], ah[mi][1], ah[mi][2], ah[mi][3], ad);
                uint32_t ad2 = aLb + ((arow + mi * 16) * 40 + k16 + acolb) * 2;
                LDSM4(al[mi][0], al[mi][1], al[mi][2], al[mi][3], ad2);
            }
#pragma unroll
            for (int ni = 0; ni < 4; ++ni) {
                uint32_t bd = bHb + ((brow + ni * 8) * 40 + k16 + bcolb) * 2;
                asm volatile("ldmatrix.sync.aligned.m8n8.x2.shared.b16 {%0,%1}, [%2];"
                             : "=r"(bh[ni][0]), "=r"(bh[ni][1]) : "r"(bd));
                uint32_t bd2 = bLb + ((brow + ni * 8) * 40 + k16 + bcolb) * 2;
                asm volatile("ldmatrix.sync.aligned.m8n8.x2.shared.b16 {%0,%1}, [%2];"
                             : "=r"(bl[ni][0]), "=r"(bl[ni][1]) : "r"(bd2));
            }
#pragma unroll
            for (int mi = 0; mi < 4; ++mi)
#pragma unroll
                for (int ni = 0; ni < 4; ++ni) {
                    MMA_OP(acc[mi][ni], ah[mi], bh[ni]);
                    MMA_OP(acc[mi][ni], ah[mi], bl[ni]);
                    MMA_OP(acc[mi][ni], al[mi], bh[ni]);
                }
        }
        __syncthreads();
    }

    const int crow = m0 + wm * 64 + (lane >> 2);
    const int ccol = n0 + wn * 32 + (lane & 3) * 2;
#pragma unroll
    for (int mi = 0; mi < 4; ++mi)
#pragma unroll
        for (int ni = 0; ni < 4; ++ni) {
            size_t r0 = (size_t)(crow + mi * 16) * DD + ccol + ni * 8;
            size_t r1 = (size_t)(crow + mi * 16 + 8) * DD + ccol + ni * 8;
            *(float2*)&C[r0] = make_float2(acc[mi][ni][0], acc[mi][ni][1]);
            *(float2*)&C[r1] = make_float2(acc[mi][ni][2], acc[mi][ni][3]);
        }
}

// ---------------------------------------------------------------------------
// Tensorized scores: S = (Q K^T + shear(Q E^T)) / 8, causal mask.
// Block 128 thr (4 warps), tile 64(q) x 64(k). U = Q·E^T is 64x128.
// smem layout (bytes): Qh 0, Ql 9216, Kh 18432, Kl 27648,
//                      Eh 36864 (128x144), El 55296, U 73728 (64x132 f32)
// ---------------------------------------------------------------------------
#define SCQH 0
#define SCQL 9216
#define SCKH 18432
#define SCKL 27648
#define SCEH 36864
#define SCEL 55296
#define SCU  73728
#define SC_SMEM (73728 + 64 * 132 * 4)   // 107520

__global__ __launch_bounds__(128)
void scores_mma(const __nv_bfloat16* __restrict__ Qh, const __nv_bfloat16* __restrict__ Ql,
                const __nv_bfloat16* __restrict__ Kh, const __nv_bfloat16* __restrict__ Kl,
                const __nv_bfloat16* __restrict__ Eh, const __nv_bfloat16* __restrict__ El) {
    const int q0 = blockIdx.y * 64;
    const int k0 = blockIdx.x * 64;
    if (k0 > q0) return;
    extern __shared__ __align__(128) char sm[];
    const uint32_t smb = smem_u32(sm);
    const int bh = blockIdx.z;
    const int b = bh >> 4, h = bh & 15;
    const int tid = threadIdx.x;
    const int w = tid >> 5, lane = tid & 31;

    // stage Q/K tiles (64 rows x 64 bf16, row stride 144B)
    {
        const __nv_bfloat16* gq = (size_t)(b * LL + q0) * DD + h * HD + (const __nv_bfloat16*)0;
        const uint4* srcQh = (const uint4*)(Qh + (size_t)(b * LL + q0) * DD + h * HD);
        const uint4* srcQl = (const uint4*)(Ql + (size_t)(b * LL + q0) * DD + h * HD);
        const uint4* srcKh = (const uint4*)(Kh + (size_t)(b * LL + k0) * DD + h * HD);
        const uint4* srcKl = (const uint4*)(Kl + (size_t)(b * LL + k0) * DD + h * HD);
        (void)gq;
#pragma unroll
        for (int t = 0; t < 16; ++t) {
            int i = tid + t * 128;             // 0..2047
            int tile = i >> 9;                 // 0..3
            int r = (i >> 3) & 63;
            int c = i & 7;
            const uint4* s4 = (tile == 0) ? srcQh : (tile == 1) ? srcQl : (tile == 2) ? srcKh : srcKl;
            uint32_t off = (tile == 0) ? SCQH : (tile == 1) ? SCQL : (tile == 2) ? SCKH : SCKL;
            *(uint4*)(sm + off + r * 144 + c * 16) = s4[(size_t)r * (DD / 8) + c];
        }
    }
    // stage E window (128 rows x 64 bf16)
    const int base0 = k0 - q0 + 961;
    {
        const uint4* sEh = (const uint4*)(Eh + (size_t)base0 * HD);
        const uint4* sEl = (const uint4*)(El + (size_t)base0 * HD);
#pragma unroll
        for (int t = 0; t < 16; ++t) {
            int i = tid + t * 128;             // 0..2047
            int tt = i >> 10;
            int r = (i >> 3) & 127;
            int c = i & 7;
            const uint4* s4 = tt ? sEl : sEh;
            uint32_t off = tt ? SCEL : SCEH;
            *(uint4*)(sm + off + r * 144 + c * 16) = s4[(size_t)r * (HD / 8) + c];
        }
    }
    __syncthreads();

    float aqk[8][4];
    float au[16][4];
#pragma unroll
    for (int i = 0; i < 8; ++i)
#pragma unroll
        for (int j = 0; j < 4; ++j) aqk[i][j] = 0.f;
#pragma unroll
    for (int i = 0; i < 16; ++i)
#pragma unroll
        for (int j = 0; j < 4; ++j) au[i][j] = 0.f;

    const int frow = (lane & 15);
    const int fcolb = (lane >> 4) << 3;

#pragma unroll
    for (int d16 = 0; d16 < 64; d16 += 16) {
        uint32_t ah[4], al[4];
        uint32_t aaddr = smb + SCQH + (w * 16 + frow) * 144 + (d16 + fcolb) * 2;
        LDSM4(ah[0], ah[1], ah[2], ah[3], aaddr);
        uint32_t aaddr2 = smb + SCQL + (w * 16 + frow) * 144 + (d16 + fcolb) * 2;
        LDSM4(al[0], al[1], al[2], al[3], aaddr2);

#pragma unroll
        for (int ng = 0; ng < 4; ++ng) {
            uint32_t kh4[4], kl4[4];
            uint32_t ba = smb + SCKH + (ng * 16 + frow) * 144 + (d16 + fcolb) * 2;
            LDSM4(kh4[0], kh4[1], kh4[2], kh4[3], ba);
            uint32_t ba2 = smb + SCKL + (ng * 16 + frow) * 144 + (d16 + fcolb) * 2;
            LDSM4(kl4[0], kl4[1], kl4[2], kl4[3], ba2);
            uint32_t f0h[2] = {kh4[0], kh4[2]}, f1h[2] = {kh4[1], kh4[3]};
            uint32_t f0l[2] = {kl4[0], kl4[2]}, f1l[2] = {kl4[1], kl4[3]};
            MMA_OP(aqk[2 * ng],     ah, f0h);
            MMA_OP(aqk[2 * ng],     ah, f0l);
            MMA_OP(aqk[2 * ng],     al, f0h);
            MMA_OP(aqk[2 * ng + 1], ah, f1h);
            MMA_OP(aqk[2 * ng + 1], ah, f1l);
            MMA_OP(aqk[2 * ng + 1], al, f1h);
        }
#pragma unroll
        for (int ng = 0; ng < 8; ++ng) {
            uint32_t e4h[4], e4l[4];
            uint32_t ba = smb + SCEH + (ng * 16 + frow) * 144 + (d16 + fcolb) * 2;
            LDSM4(e4h[0], e4h[1], e4h[2], e4h[3], ba);
            uint32_t ba2 = smb + SCEL + (ng * 16 + frow) * 144 + (d16 + fcolb) * 2;
            LDSM4(e4l[0], e4l[1], e4l[2], e4l[3], ba2);
            uint32_t f0h[2] = {e4h[0], e4h[2]}, f1h[2] = {e4h[1], e4h[3]};
            uint32_t f0l[2] = {e4l[0], e4l[2]}, f1l[2] = {e4l[1], e4l[3]};
            MMA_OP(au[2 * ng],     ah, f0h);
            MMA_OP(au[2 * ng],     ah, f0l);
            MMA_OP(au[2 * ng],     al, f0h);
            MMA_OP(au[2 * ng + 1], ah, f1h);
            MMA_OP(au[2 * ng + 1], ah, f1l);
            MMA_OP(au[2 * ng + 1], al, f1h);
        }
    }

    // write U accum to smem
    float* Us = (float*)(sm + SCU);
    const int crow = w * 16 + (lane >> 2);
    const int ccol = (lane & 3) * 2;
#pragma unroll
    for (int ni = 0; ni < 16; ++ni) {
        *(float2*)&Us[crow * 132 + ni * 8 + ccol]       = make_float2(au[ni][0], au[ni][1]);
        *(float2*)&Us[(crow + 8) * 132 + ni * 8 + ccol] = make_float2(au[ni][2], au[ni][3]);
    }
    __syncthreads();

    float* Sg = g_S + ((size_t)bh << 20);
#pragma unroll
    for (int ni = 0; ni < 8; ++ni) {
        int kl = ni * 8 + ccol;
#pragma unroll
        for (int half = 0; half < 2; ++half) {
            int ql = crow + half * 8;
            int r = kl - ql + 63;
            float u0 = Us[ql * 132 + r], u1 = Us[ql * 132 + r + 1];
            float v0 = (aqk[ni][half * 2]     + u0) * 0.125f;
            float v1 = (aqk[ni][half * 2 + 1] + u1) * 0.125f;
            int qg = q0 + ql, kg = k0 + kl;
            if (kg > qg) v0 = -1e30f;
            if (kg + 1 > qg) v1 = -1e30f;
            *(float2*)&Sg[(size_t)qg * 1024 + kg] = make_float2(v0, v1);
        }
    }
}

// ---------------------------------------------------------------------------
// Row softmax with causal mask (unchanged)
// ---------------------------------------------------------------------------
__global__ __launch_bounds__(256)
void softmax_kernel() {
    const int row = blockIdx.x;
    const int q = row & 1023;
    float* Sr = g_S + (size_t)row * 1024;
    const int tid = threadIdx.x;

    float v[4];
    float mx = -1e30f;
#pragma unroll
    for (int t = 0; t < 4; ++t) {
        int k = tid + t * 256;
        v[t] = (k <= q) ? Sr[k] : -1e30f;
        mx = fmaxf(mx, v[t]);
    }
    __shared__ float red[8];
#pragma unroll
    for (int o = 16; o; o >>= 1) mx = fmaxf(mx, __shfl_xor_sync(0xffffffffu, mx, o));
    if ((tid & 31) == 0) red[tid >> 5] = mx;
    __syncthreads();
    float m = red[0];
#pragma unroll
    for (int i = 1; i < 8; ++i) m = fmaxf(m, red[i]);
    __syncthreads();

    float s = 0.f;
#pragma unroll
    for (int t = 0; t < 4; ++t) {
        int k = tid + t * 256;
        v[t] = (k <= q) ? expf(v[t] - m) : 0.f;
        s += v[t];
    }
#pragma unroll
    for (int o = 16; o; o >>= 1) s += __shfl_xor_sync(0xffffffffu, s, o);
    if ((tid & 31) == 0) red[tid >> 5] = s;
    __syncthreads();
    float tot = 0.f;
#pragma unroll
    for (int i = 0; i < 8; ++i) tot += red[i];
    float inv = 1.f / tot;
#pragma unroll
    for (int t = 0; t < 4; ++t) {
        int k = tid + t * 256;
        Sr[k] = v[t] * inv;
    }
}

// ---------------------------------------------------------------------------
// Tensorized output: O = P·V + shear(P)·E   (per bh, per 64-q tile)
// smem (bytes): Ph 0 (64x144), Pl 9216, Pdh 18432 (64x272), Pdl 35840,
//               Vh 53248, Vl 62464, Eh 71680 (128x144), El 90112; tot 108544
// ---------------------------------------------------------------------------
#define OPH  0
#define OPL  9216
#define OPDH 18432
#define OPDL 35840
#define OVH  53248
#define OVL  62464
#define OEH  71680
#define OEL  90112
#define OUT_SMEM 108544

__global__ __launch_bounds__(128)
void out_mma(const __nv_bfloat16* __restrict__ Vh, const __nv_bfloat16* __restrict__ Vl,
             const __nv_bfloat16* __restrict__ Eh, const __nv_bfloat16* __restrict__ El) {
    extern __shared__ __align__(128) char sm[];
    const uint32_t smb = smem_u32(sm);
    const int q0 = blockIdx.x * 64;
    const int bh = blockIdx.y;
    const int b = bh >> 4, h = bh & 15;
    const int tid = threadIdx.x;
    const int w = tid >> 5, lane = tid & 31;
    const int frow = (lane & 15);
    const int fcolb = (lane >> 4) << 3;

    const float* Pg = g_S + ((size_t)bh << 20);

    float acc[8][4];
#pragma unroll
    for (int i = 0; i < 8; ++i)
#pragma unroll
        for (int j = 0; j < 4; ++j) acc[i][j] = 0.f;

    for (int k0 = 0; k0 <= q0; k0 += 64) {
        // stage P (fp32 -> Ph/Pl + sheared Pdh/Pdl)
#pragma unroll
        for (int t = 0; t < 8; ++t) {
            int i = tid + t * 128;             // 0..1023
            int ql = i >> 4;
            int c4 = (i & 15) * 4;
            float4 p = *(const float4*)&Pg[(size_t)(q0 + ql) * 1024 + k0 + c4];
            __nv_bfloat16 h0 = __float2bfloat16(p.x), h1 = __float2bfloat16(p.y);
            __nv_bfloat16 h2 = __float2bfloat16(p.z), h3 = __float2bfloat16(p.w);
            __nv_bfloat16 l0 = __float2bfloat16(p.x - __bfloat162float(h0));
            __nv_bfloat16 l1 = __float2bfloat16(p.y - __bfloat162float(h1));
            __nv_bfloat16 l2 = __float2bfloat16(p.z - __bfloat162float(h2));
            __nv_bfloat16 l3 = __float2bfloat16(p.w - __bfloat162float(h3));
            *(uint2*)(sm + OPH + ql * 144 + c4 * 2) = make_uint2(pack2(h0, h1), pack2(h2, h3));
            *(uint2*)(sm + OPL + ql * 144 + c4 * 2) = make_uint2(pack2(l0, l1), pack2(l2, l3));
            __nv_bfloat16 hs[4] = {h0, h1, h2, h3};
            __nv_bfloat16 ls[4] = {l0, l1, l2, l3};
#pragma unroll
            for (int j = 0; j < 4; ++j) {
                int r = (c4 + j) - ql + 63;        // 0..126
                *(uint16_t*)(sm + OPDH + ql * 272 + r * 2) = bf16bits(hs[j]);
                *(uint16_t*)(sm + OPDL + ql * 272 + r * 2) = bf16bits(ls[j]);
                int rz = (r + 64) & 127;
                *(uint16_t*)(sm + OPDH + ql * 272 + rz * 2) = 0;
                *(uint16_t*)(sm + OPDL + ql * 272 + rz * 2) = 0;
            }
        }
        // stage V (64x64 bf16 hi/lo)
        {
            const uint4* sVh = (const uint4*)(Vh + (size_t)(b * LL + k0) * DD + h * HD);
            const uint4* sVl = (const uint4*)(Vl + (size_t)(b * LL + k0) * DD + h * HD);
#pragma unroll
            for (int t = 0; t < 8; ++t) {
                int i = tid + t * 128;         // 0..1023
                int tt = i >> 9;
                int r = (i >> 3) & 63;
                int c = i & 7;
                const uint4* s4 = tt ? sVl : sVh;
                uint32_t off = tt ? OVL : OVH;
                *(uint4*)(sm + off + r * 144 + c * 16) = s4[(size_t)r * (DD / 8) + c];
            }
        }
        // stage E window (128x64)
        const int base0 = k0 - q0 + 961;
        {
            const uint4* sEh = (const uint4*)(Eh + (size_t)base0 * HD);
            const uint4* sEl = (const uint4*)(El + (size_t)base0 * HD);
#pragma unroll
            for (int t = 0; t < 16; ++t) {
                int i = tid + t * 128;
                int tt = i >> 10;
                int r = (i >> 3) & 127;
                int c = i & 7;
                const uint4* s4 = tt ? sEl : sEh;
                uint32_t off = tt ? OEL : OEH;
                *(uint4*)(sm + off + r * 144 + c * 16) = s4[(size_t)r * (HD / 8) + c];
            }
        }
        __syncthreads();

        // P·V part (contraction over k, 64)
#pragma unroll
        for (int k16 = 0; k16 < 64; k16 += 16) {
            uint32_t ph[4], pl[4];
            LDSM4(ph[0], ph[1], ph[2], ph[3], smb + OPH + (w * 16 + frow) * 144 + (k16 + fcolb) * 2);
            LDSM4(pl[0], pl[1], pl[2], pl[3], smb + OPL + (w * 16 + frow) * 144 + (k16 + fcolb) * 2);
#pragma unroll
            for (int ng = 0; ng < 4; ++ng) {
                uint32_t vh4[4], vl4[4];
                uint32_t ba = smb + OVH + (k16 + frow) * 144 + (ng * 16 + fcolb) * 2;
                LDSM4T(vh4[0], vh4[1], vh4[2], vh4[3], ba);
                uint32_t ba2 = smb + OVL + (k16 + frow) * 144 + (ng * 16 + fcolb) * 2;
                LDSM4T(vl4[0], vl4[1], vl4[2], vl4[3], ba2);
                uint32_t f0h[2] = {vh4[0], vh4[1]}, f1h[2] = {vh4[2], vh4[3]};
                uint32_t f0l[2] = {vl4[0], vl4[1]}, f1l[2] = {vl4[2], vl4[3]};
                MMA_OP(acc[2 * ng],     ph, f0h);
                MMA_OP(acc[2 * ng],     ph, f0l);
                MMA_OP(acc[2 * ng],     pl, f0h);
                MMA_OP(acc[2 * ng + 1], ph, f1h);
                MMA_OP(acc[2 * ng + 1], ph, f1l);
                MMA_OP(acc[2 * ng + 1], pl, f1h);
            }
        }
        // Pd·E part (contraction over r, 128)
#pragma unroll
        for (int r16 = 0; r16 < 128; r16 += 16) {
            uint32_t ph[4], pl[4];
            LDSM4(ph[0], ph[1], ph[2], ph[3], smb + OPDH + (w * 16 + frow) * 272 + (r16 + fcolb) * 2);
            LDSM4(pl[0], pl[1], pl[2], pl[3], smb + OPDL + (w * 16 + frow) * 272 + (r16 + fcolb) * 2);
#pragma unroll
            for (int ng = 0; ng < 4; ++ng) {
                uint32_t eh4[4], el4[4];
                uint32_t ba = smb + OEH + (r16 + frow) * 144 + (ng * 16 + fcolb) * 2;
                LDSM4T(eh4[0], eh4[1], eh4[2], eh4[3], ba);
                uint32_t ba2 = smb + OEL + (r16 + frow) * 144 + (ng * 16 + fcolb) * 2;
                LDSM4T(el4[0], el4[1], el4[2], el4[3], ba2);
                uint32_t f0h[2] = {eh4[0], eh4[1]}, f1h[2] = {eh4[2], eh4[3]};
                uint32_t f0l[2] = {el4[0], el4[1]}, f1l[2] = {el4[2], el4[3]};
                MMA_OP(acc[2 * ng],     ph, f0h);
                MMA_OP(acc[2 * ng],     ph, f0l);
                MMA_OP(acc[2 * ng],     pl, f0h);
                MMA_OP(acc[2 * ng + 1], ph, f1h);
                MMA_OP(acc[2 * ng + 1], ph, f1l);
                MMA_OP(acc[2 * ng + 1], pl, f1h);
            }
        }
        __syncthreads();
    }

    float* Og = g_O + (size_t)(b * LL + q0) * DD + h * HD;
    const int crow = w * 16 + (lane >> 2);
    const int ccol = (lane & 3) * 2;
#pragma unroll
    for (int ni = 0; ni < 8; ++ni) {
        *(float2*)&Og[(size_t)crow * DD + ni * 8 + ccol]       = make_float2(acc[ni][0], acc[ni][1]);
        *(float2*)&Og[(size_t)(crow + 8) * DD + ni * 8 + ccol] = make_float2(acc[ni][2], acc[ni][3]);
    }
}

// ---------------------------------------------------------------------------
// Launch
// ---------------------------------------------------------------------------
extern "C" void kernel_launch(void* const* d_in, const int* in_sizes, int n_in,
                              void* d_out, int out_size) {
    const float* x   = (const float*)d_in[0];
    const float* Wq  = (const float*)d_in[1];
    const float* Wk  = (const float*)d_in[2];
    const float* Wv  = (const float*)d_in[3];
    const float* Wo  = (const float*)d_in[4];
    const float* pek = (const float*)d_in[5];
    const float* pev = (const float*)d_in[6];
    float* out = (float*)d_out;

    float *Q, *K, *V, *O;
    __nv_bfloat16 *xh, *xl, *wh, *wl, *Qh, *Ql, *Kh, *Kl, *Vh, *Vl;
    __nv_bfloat16 *pekh, *pekl, *pevh, *pevl;
    cudaGetSymbolAddress((void**)&Q, g_Q);
    cudaGetSymbolAddress((void**)&K, g_K);
    cudaGetSymbolAddress((void**)&V, g_V);
    cudaGetSymbolAddress((void**)&O, g_O);
    cudaGetSymbolAddress((void**)&xh, g_xh);
    cudaGetSymbolAddress((void**)&xl, g_xl);
    cudaGetSymbolAddress((void**)&wh, g_wh);
    cudaGetSymbolAddress((void**)&wl, g_wl);
    cudaGetSymbolAddress((void**)&Qh, g_Qh);
    cudaGetSymbolAddress((void**)&Ql, g_Ql);
    cudaGetSymbolAddress((void**)&Kh, g_Kh);
    cudaGetSymbolAddress((void**)&Kl, g_Kl);
    cudaGetSymbolAddress((void**)&Vh, g_Vh);
    cudaGetSymbolAddress((void**)&Vl, g_Vl);
    cudaGetSymbolAddress((void**)&pekh, g_pekh);
    cudaGetSymbolAddress((void**)&pekl, g_pekl);
    cudaGetSymbolAddress((void**)&pevh, g_pevh);
    cudaGetSymbolAddress((void**)&pevl, g_pevl);

    cudaFuncSetAttribute(gemm_mma, cudaFuncAttributeMaxDynamicSharedMemorySize, GEMM_SMEM);
    cudaFuncSetAttribute(scores_mma, cudaFuncAttributeMaxDynamicSharedMemorySize, SC_SMEM);
    cudaFuncSetAttribute(out_mma, cudaFuncAttributeMaxDynamicSharedMemorySize, OUT_SMEM);

    const int n4x = MROWS * DD / 4;
    const int n4w = DD * DD / 4;
    const int n4p = PEN * HD / 4;        // 32784
    dim3 ggemm(DD / 128, MROWS / 128);

    split_kernel<<<(n4x + 255) / 256, 256>>>(x, xh, xl, n4x);

    split_kernel<<<(n4w + 255) / 256, 256>>>(Wq, wh, wl, n4w);
    gemm_mma<<<ggemm, 256, GEMM_SMEM>>>(xh, xl, wh, wl, Q);
    split_kernel<<<(n4w + 255) / 256, 256>>>(Wk, wh, wl, n4w);
    gemm_mma<<<ggemm, 256, GEMM_SMEM>>>(xh, xl, wh, wl, K);
    split_kernel<<<(n4w + 255) / 256, 256>>>(Wv, wh, wl, n4w);
    gemm_mma<<<ggemm, 256, GEMM_SMEM>>>(xh, xl, wh, wl, V);

    split_kernel<<<(n4x + 255) / 256, 256>>>(Q, Qh, Ql, n4x);
    split_kernel<<<(n4x + 255) / 256, 256>>>(K, Kh, Kl, n4x);
    split_kernel<<<(n4x + 255) / 256, 256>>>(V, Vh, Vl, n4x);
    split_kernel<<<(n4p + 255) / 256, 256>>>(pek, pekh, pekl, n4p);
    split_kernel<<<(n4p + 255) / 256, 256>>>(pev, pevh, pevl, n4p);

    scores_mma<<<dim3(16, 16, 64), 128, SC_SMEM>>>(Qh, Ql, Kh, Kl, pekh, pekl);
    softmax_kernel<<<64 * 1024, 256>>>();
    out_mma<<<dim3(16, 64), 128, OUT_SMEM>>>(Vh, Vl, pevh, pevl);

    split_kernel<<<(n4x + 255) / 256, 256>>>(O, xh, xl, n4x);
    split_kernel<<<(n4w + 255) / 256, 256>>>(Wo, wh, wl, n4w);
    gemm_mma<<<ggemm, 256, GEMM_SMEM>>>(xh, xl, wh, wl, out);
}

// round 9
// speedup vs baseline: 2.1752x; 1.1034x over previous
#include <cuda_runtime.h>
#include <cuda_bf16.h>
#include <cstdint>

// Problem constants
#define BB 4
#define LL 1024
#define DD 1024
#define HH 16
#define HD 64
#define MROWS 4096           // B*L
#define PEN 2049

// Scratch (device globals; allocation is forbidden)
__device__ __nv_bfloat16 g_xh[MROWS * DD];
__device__ __nv_bfloat16 g_xl[MROWS * DD];
__device__ __nv_bfloat16 g_wh[DD * DD];
__device__ __nv_bfloat16 g_wl[DD * DD];
__device__ __nv_bfloat16 g_Qh[MROWS * DD];
__device__ __nv_bfloat16 g_Ql[MROWS * DD];
__device__ __nv_bfloat16 g_Kh[MROWS * DD];
__device__ __nv_bfloat16 g_Kl[MROWS * DD];
__device__ __nv_bfloat16 g_Vh[MROWS * DD];
__device__ __nv_bfloat16 g_Vl[MROWS * DD];
__device__ __nv_bfloat16 g_Oh[MROWS * DD];
__device__ __nv_bfloat16 g_Ol[MROWS * DD];
__device__ __nv_bfloat16 g_pekh[PEN * HD];
__device__ __nv_bfloat16 g_pekl[PEN * HD];
__device__ __nv_bfloat16 g_pevh[PEN * HD];
__device__ __nv_bfloat16 g_pevl[PEN * HD];

__device__ __forceinline__ uint32_t smem_u32(const void* p) {
    uint32_t a;
    asm("{ .reg .u64 t; cvta.to.shared.u64 t, %1; cvt.u32.u64 %0, t; }" : "=r"(a) : "l"(p));
    return a;
}

#define MMA_OP(c, af, bf) \
    asm volatile("mma.sync.aligned.m16n8k16.row.col.f32.bf16.bf16.f32 " \
                 "{%0,%1,%2,%3}, {%4,%5,%6,%7}, {%8,%9}, {%0,%1,%2,%3};" \
                 : "+f"((c)[0]), "+f"((c)[1]), "+f"((c)[2]), "+f"((c)[3]) \
                 : "r"((af)[0]), "r"((af)[1]), "r"((af)[2]), "r"((af)[3]), \
                   "r"((bf)[0]), "r"((bf)[1]))

#define LDSM4(d0,d1,d2,d3,a) \
    asm volatile("ldmatrix.sync.aligned.m8n8.x4.shared.b16 {%0,%1,%2,%3}, [%4];" \
                 : "=r"(d0), "=r"(d1), "=r"(d2), "=r"(d3) : "r"(a))
#define LDSM4T(d0,d1,d2,d3,a) \
    asm volatile("ldmatrix.sync.aligned.m8n8.x4.trans.shared.b16 {%0,%1,%2,%3}, [%4];" \
                 : "=r"(d0), "=r"(d1), "=r"(d2), "=r"(d3) : "r"(a))

__device__ __forceinline__ uint32_t pack2(__nv_bfloat16 a, __nv_bfloat16 b) {
    __nv_bfloat162 t(a, b);
    return *reinterpret_cast<uint32_t*>(&t);
}
__device__ __forceinline__ uint16_t bf16bits(__nv_bfloat16 h) {
    return *reinterpret_cast<uint16_t*>(&h);
}

// ---------------------------------------------------------------------------
// fp32 -> bf16 hi/lo split
// ---------------------------------------------------------------------------
__global__ __launch_bounds__(256)
void split_kernel(const float* __restrict__ s, __nv_bfloat16* __restrict__ h,
                  __nv_bfloat16* __restrict__ l, int n4) {
    int i = blockIdx.x * 256 + threadIdx.x;
    if (i >= n4) return;
    float4 v = ((const float4*)s)[i];
    __nv_bfloat16 h0 = __float2bfloat16(v.x);
    __nv_bfloat16 h1 = __float2bfloat16(v.y);
    __nv_bfloat16 h2 = __float2bfloat16(v.z);
    __nv_bfloat16 h3 = __float2bfloat16(v.w);
    __nv_bfloat16 l0 = __float2bfloat16(v.x - __bfloat162float(h0));
    __nv_bfloat16 l1 = __float2bfloat16(v.y - __bfloat162float(h1));
    __nv_bfloat16 l2 = __float2bfloat16(v.z - __bfloat162float(h2));
    __nv_bfloat16 l3 = __float2bfloat16(v.w - __bfloat162float(h3));
    ((uint2*)h)[i] = make_uint2(pack2(h0, h1), pack2(h2, h3));
    ((uint2*)l)[i] = make_uint2(pack2(l0, l1), pack2(l2, l3));
}

// ---------------------------------------------------------------------------
// mma.sync bf16x3 GEMM: C = A * B^T. If Ch != null, emit bf16 hi/lo split
// instead of fp32 (for projection GEMMs feeding the attention kernel).
// ---------------------------------------------------------------------------
#define GKDIM 1024
#define NIT 32
#define TILE_B 10240
#define STAGE_B (4 * TILE_B)
#define GEMM_SMEM (2 * STAGE_B)

__global__ __launch_bounds__(256, 1)
void gemm_mma(const __nv_bfloat16* __restrict__ Ah, const __nv_bfloat16* __restrict__ Al,
              const __nv_bfloat16* __restrict__ Bh, const __nv_bfloat16* __restrict__ Bl,
              float* __restrict__ C,
              __nv_bfloat16* __restrict__ Ch, __nv_bfloat16* __restrict__ Cl) {
    extern __shared__ __align__(128) char sm[];
    const uint32_t smb = smem_u32(sm);
    const int tid = threadIdx.x;
    const int wid = tid >> 5, lane = tid & 31;
    const int m0 = blockIdx.y * 128, n0 = blockIdx.x * 128;
    const int wm = wid & 1, wn = wid >> 1;

    const __nv_bfloat16* srcs[4] = {
        Ah + (size_t)m0 * GKDIM, Al + (size_t)m0 * GKDIM,
        Bh + (size_t)n0 * GKDIM, Bl + (size_t)n0 * GKDIM };

    auto stage_load = [&](int kc, int s) {
#pragma unroll
        for (int rep = 0; rep < 8; ++rep) {
            int idx = tid + rep * 256;
            int tile = idx >> 9;
            int r = (idx >> 2) & 127;
            int c = idx & 3;
            const void* gp = srcs[tile] + (size_t)r * GKDIM + kc * 32 + c * 8;
            uint32_t dp = smb + s * STAGE_B + tile * TILE_B + r * 80 + c * 16;
            asm volatile("cp.async.cg.shared.global [%0], [%1], 16;" :: "r"(dp), "l"(gp));
        }
        asm volatile("cp.async.commit_group;");
    };

    float acc[4][4][4];
#pragma unroll
    for (int i = 0; i < 4; ++i)
#pragma unroll
        for (int j = 0; j < 4; ++j)
#pragma unroll
            for (int k = 0; k < 4; ++k) acc[i][j][k] = 0.f;

    stage_load(0, 0);

    for (int it = 0; it < NIT; ++it) {
        if (it + 1 < NIT) {
            stage_load(it + 1, (it + 1) & 1);
            asm volatile("cp.async.wait_group 1;");
        } else {
            asm volatile("cp.async.wait_group 0;");
        }
        __syncthreads();

        const uint32_t base = smb + (it & 1) * STAGE_B;
        const uint32_t aHb = base, aLb = base + TILE_B;
        const uint32_t bHb = base + 2 * TILE_B, bLb = base + 3 * TILE_B;
        const int arow = wm * 64 + (lane & 15);
        const int acolb = (lane & 16) >> 1;
        const int brow = wn * 32 + (lane & 7);
        const int bcolb = lane & 8;

#pragma unroll
        for (int k16 = 0; k16 < 32; k16 += 16) {
            uint32_t ah[4][4], al[4][4], bh[4][2], bl[4][2];
#pragma unroll
            for (int mi = 0; mi < 4; ++mi) {
                uint32_t ad = aHb + ((arow + mi * 16) * 40 + k16 + acolb) * 2;
                LDSM4(ah[mi][0], ah[mi][1], ah[mi][2], ah[mi][3], ad);
                uint32_t ad2 = aLb + ((arow + mi * 16) * 40 + k16 + acolb) * 2;
                LDSM4(al[mi][0], al[mi][1], al[mi][2], al[mi][3], ad2);
            }
#pragma unroll
            for (int ni = 0; ni < 4; ++ni) {
                uint32_t bd = bHb + ((brow + ni * 8) * 40 + k16 + bcolb) * 2;
                asm volatile("ldmatrix.sync.aligned.m8n8.x2.shared.b16 {%0,%1}, [%2];"
                             : "=r"(bh[ni][0]), "=r"(bh[ni][1]) : "r"(bd));
                uint32_t bd2 = bLb + ((brow + ni * 8) * 40 + k16 + bcolb) * 2;
                asm volatile("ldmatrix.sync.aligned.m8n8.x2.shared.b16 {%0,%1}, [%2];"
                             : "=r"(bl[ni][0]), "=r"(bl[ni][1]) : "r"(bd2));
            }
#pragma unroll
            for (int mi = 0; mi < 4; ++mi)
#pragma unroll
                for (int ni = 0; ni < 4; ++ni) {
                    MMA_OP(acc[mi][ni], ah[mi], bh[ni]);
                    MMA_OP(acc[mi][ni], ah[mi], bl[ni]);
                    MMA_OP(acc[mi][ni], al[mi], bh[ni]);
                }
        }
        __syncthreads();
    }

    const int crow = m0 + wm * 64 + (lane >> 2);
    const int ccol = n0 + wn * 32 + (lane & 3) * 2;
    if (Ch) {
#pragma unroll
        for (int mi = 0; mi < 4; ++mi)
#pragma unroll
            for (int ni = 0; ni < 4; ++ni) {
                size_t r0 = (size_t)(crow + mi * 16) * DD + ccol + ni * 8;
                size_t r1 = (size_t)(crow + mi * 16 + 8) * DD + ccol + ni * 8;
#pragma unroll
                for (int half = 0; half < 2; ++half) {
                    float v0 = acc[mi][ni][half * 2], v1 = acc[mi][ni][half * 2 + 1];
                    __nv_bfloat16 h0 = __float2bfloat16(v0), h1 = __float2bfloat16(v1);
                    __nv_bfloat16 q0b = __float2bfloat16(v0 - __bfloat162float(h0));
                    __nv_bfloat16 q1b = __float2bfloat16(v1 - __bfloat162float(h1));
                    size_t r = half ? r1 : r0;
                    *(uint32_t*)&Ch[r] = pack2(h0, h1);
                    *(uint32_t*)&Cl[r] = pack2(q0b, q1b);
                }
            }
    } else {
#pragma unroll
        for (int mi = 0; mi < 4; ++mi)
#pragma unroll
            for (int ni = 0; ni < 4; ++ni) {
                size_t r0 = (size_t)(crow + mi * 16) * DD + ccol + ni * 8;
                size_t r1 = (size_t)(crow + mi * 16 + 8) * DD + ccol + ni * 8;
                *(float2*)&C[r0] = make_float2(acc[mi][ni][0], acc[mi][ni][1]);
                *(float2*)&C[r1] = make_float2(acc[mi][ni][2], acc[mi][ni][3]);
            }
    }
}

// ---------------------------------------------------------------------------
// Fused flash attention with relative position bias (K and V side).
// One CTA (128 thr) per (bh, 64-row q-tile); loops over k-tiles with online
// softmax. Sheared Pd buffer staged with scalar STS; BOTH pek and pev windows
// staged at base k0-q0+961 to match the r = kl-ql+63 shear convention.
// ---------------------------------------------------------------------------
#define AQH   0
#define AQL   9216
#define AKH   18432
#define AKL   27648
#define AVH   36864
#define AVL   46080
#define AEKH  55296
#define AEKL  73728
#define AEVH  92160
#define AEVL  110592
#define AU    129024
#define APH   162816
#define APL   172032
#define APDH  181248
#define APDL  198656
#define ASTAT 216064
#define ATTN_SMEM (216064 + 768)

__global__ __launch_bounds__(128)
void attn_fused(const __nv_bfloat16* __restrict__ Qh, const __nv_bfloat16* __restrict__ Ql,
                const __nv_bfloat16* __restrict__ Kh, const __nv_bfloat16* __restrict__ Kl,
                const __nv_bfloat16* __restrict__ Vh, const __nv_bfloat16* __restrict__ Vl,
                const __nv_bfloat16* __restrict__ Ekh, const __nv_bfloat16* __restrict__ Ekl,
                const __nv_bfloat16* __restrict__ Evh, const __nv_bfloat16* __restrict__ Evl,
                __nv_bfloat16* __restrict__ Oh, __nv_bfloat16* __restrict__ Ol) {
    extern __shared__ __align__(128) char sm[];
    const uint32_t smb = smem_u32(sm);
    const int qt = 15 - blockIdx.x;           // heavy tiles first
    const int q0 = qt * 64;
    const int bh = blockIdx.y;
    const int b = bh >> 4, h = bh & 15;
    const int tid = threadIdx.x;
    const int w = tid >> 5, lane = tid & 31;
    const int frow = lane & 15;
    const int fcolb = (lane >> 4) << 3;
    const int crow = w * 16 + (lane >> 2);
    const int ccol = (lane & 3) * 2;

    float* mS = (float*)(sm + ASTAT);
    float* lS = mS + 64;
    float* fS = mS + 128;
    float* Us = (float*)(sm + AU);

    if (tid < 64) { mS[tid] = -1e30f; lS[tid] = 0.f; }

    // stage Q (once)
    {
        const uint4* sQh = (const uint4*)(Qh + (size_t)(b * LL + q0) * DD + h * HD);
        const uint4* sQl = (const uint4*)(Ql + (size_t)(b * LL + q0) * DD + h * HD);
#pragma unroll
        for (int t = 0; t < 8; ++t) {
            int i = tid + t * 128;
            int tt = i >> 9;
            int r = (i >> 3) & 63;
            int c = i & 7;
            const uint4* s4 = tt ? sQl : sQh;
            uint32_t off = tt ? AQL : AQH;
            *(uint4*)(sm + off + r * 144 + c * 16) = s4[(size_t)r * (DD / 8) + c];
        }
    }

    float acc[8][4];
#pragma unroll
    for (int i = 0; i < 8; ++i)
#pragma unroll
        for (int j = 0; j < 4; ++j) acc[i][j] = 0.f;

    for (int k0 = 0; k0 <= q0; k0 += 64) {
        __syncthreads();   // previous iteration's MMA reads done; safe to restage
        // stage K, V (64x64 each, hi/lo)
        {
            const uint4* sKh = (const uint4*)(Kh + (size_t)(b * LL + k0) * DD + h * HD);
            const uint4* sKl = (const uint4*)(Kl + (size_t)(b * LL + k0) * DD + h * HD);
            const uint4* sVh = (const uint4*)(Vh + (size_t)(b * LL + k0) * DD + h * HD);
            const uint4* sVl = (const uint4*)(Vl + (size_t)(b * LL + k0) * DD + h * HD);
#pragma unroll
            for (int t = 0; t < 16; ++t) {
                int i = tid + t * 128;         // 0..2047
                int tile = i >> 9;             // 0..3
                int r = (i >> 3) & 63;
                int c = i & 7;
                const uint4* s4 = (tile == 0) ? sKh : (tile == 1) ? sKl : (tile == 2) ? sVh : sVl;
                uint32_t off = (tile == 0) ? AKH : (tile == 1) ? AKL : (tile == 2) ? AVH : AVL;
                *(uint4*)(sm + off + r * 144 + c * 16) = s4[(size_t)r * (DD / 8) + c];
            }
        }
        // stage pek AND pev windows, both at base k0-q0+961, 128x64 each
        {
            const uint4* sEkh = (const uint4*)(Ekh + (size_t)(k0 - q0 + 961) * HD);
            const uint4* sEkl = (const uint4*)(Ekl + (size_t)(k0 - q0 + 961) * HD);
            const uint4* sEvh = (const uint4*)(Evh + (size_t)(k0 - q0 + 961) * HD);
            const uint4* sEvl = (const uint4*)(Evl + (size_t)(k0 - q0 + 961) * HD);
#pragma unroll
            for (int t = 0; t < 32; ++t) {
                int i = tid + t * 128;         // 0..4095
                int tile = i >> 10;            // 0..3
                int r = (i >> 3) & 127;
                int c = i & 7;
                const uint4* s4 = (tile == 0) ? sEkh : (tile == 1) ? sEkl : (tile == 2) ? sEvh : sEvl;
                uint32_t off = (tile == 0) ? AEKH : (tile == 1) ? AEKL : (tile == 2) ? AEVH : AEVL;
                *(uint4*)(sm + off + r * 144 + c * 16) = s4[(size_t)r * (HD / 8) + c];
            }
        }
        __syncthreads();

        // ---- S = Q·K^T (aqk) and U = Q·Ek^T (au) ----
        float aqk[8][4], au[16][4];
#pragma unroll
        for (int i = 0; i < 8; ++i)
#pragma unroll
            for (int j = 0; j < 4; ++j) aqk[i][j] = 0.f;
#pragma unroll
        for (int i = 0; i < 16; ++i)
#pragma unroll
            for (int j = 0; j < 4; ++j) au[i][j] = 0.f;

#pragma unroll
        for (int d16 = 0; d16 < 64; d16 += 16) {
            uint32_t ah[4], al[4];
            LDSM4(ah[0], ah[1], ah[2], ah[3], smb + AQH + (w * 16 + frow) * 144 + (d16 + fcolb) * 2);
            LDSM4(al[0], al[1], al[2], al[3], smb + AQL + (w * 16 + frow) * 144 + (d16 + fcolb) * 2);
#pragma unroll
            for (int ng = 0; ng < 4; ++ng) {
                uint32_t kh4[4], kl4[4];
                LDSM4(kh4[0], kh4[1], kh4[2], kh4[3],
                      smb + AKH + (ng * 16 + frow) * 144 + (d16 + fcolb) * 2);
                LDSM4(kl4[0], kl4[1], kl4[2], kl4[3],
                      smb + AKL + (ng * 16 + frow) * 144 + (d16 + fcolb) * 2);
                uint32_t f0h[2] = {kh4[0], kh4[2]}, f1h[2] = {kh4[1], kh4[3]};
                uint32_t f0l[2] = {kl4[0], kl4[2]}, f1l[2] = {kl4[1], kl4[3]};
                MMA_OP(aqk[2 * ng],     ah, f0h);
                MMA_OP(aqk[2 * ng],     ah, f0l);
                MMA_OP(aqk[2 * ng],     al, f0h);
                MMA_OP(aqk[2 * ng + 1], ah, f1h);
                MMA_OP(aqk[2 * ng + 1], ah, f1l);
                MMA_OP(aqk[2 * ng + 1], al, f1h);
            }
#pragma unroll
            for (int ng = 0; ng < 8; ++ng) {
                uint32_t e4h[4], e4l[4];
                LDSM4(e4h[0], e4h[1], e4h[2], e4h[3],
                      smb + AEKH + (ng * 16 + frow) * 144 + (d16 + fcolb) * 2);
                LDSM4(e4l[0], e4l[1], e4l[2], e4l[3],
                      smb + AEKL + (ng * 16 + frow) * 144 + (d16 + fcolb) * 2);
                uint32_t f0h[2] = {e4h[0], e4h[2]}, f1h[2] = {e4h[1], e4h[3]};
                uint32_t f0l[2] = {e4l[0], e4l[2]}, f1l[2] = {e4l[1], e4l[3]};
                MMA_OP(au[2 * ng],     ah, f0h);
                MMA_OP(au[2 * ng],     ah, f0l);
                MMA_OP(au[2 * ng],     al, f0h);
                MMA_OP(au[2 * ng + 1], ah, f1h);
                MMA_OP(au[2 * ng + 1], ah, f1l);
                MMA_OP(au[2 * ng + 1], al, f1h);
            }
        }

        // write U to smem
#pragma unroll
        for (int ni = 0; ni < 16; ++ni) {
            Us[crow * 132 + ni * 8 + ccol]           = au[ni][0];
            Us[crow * 132 + ni * 8 + ccol + 1]       = au[ni][1];
            Us[(crow + 8) * 132 + ni * 8 + ccol]     = au[ni][2];
            Us[(crow + 8) * 132 + ni * 8 + ccol + 1] = au[ni][3];
        }
        __syncthreads();

        // ---- online softmax + P / sheared-Pd staging ----
#pragma unroll
        for (int hf = 0; hf < 2; ++hf) {
            int row = crow + hf * 8;
            int qg = q0 + row;
            float p[16];
            float mx = -1e30f;
#pragma unroll
            for (int ni = 0; ni < 8; ++ni) {
#pragma unroll
                for (int c = 0; c < 2; ++c) {
                    int kl = ni * 8 + ccol + c;
                    int r = kl - row + 63;
                    float s = (aqk[ni][hf * 2 + c] + Us[row * 132 + r]) * 0.125f;
                    if (k0 + kl > qg) s = -1e30f;
                    p[ni * 2 + c] = s;
                    mx = fmaxf(mx, s);
                }
            }
            mx = fmaxf(mx, __shfl_xor_sync(0xffffffffu, mx, 1));
            mx = fmaxf(mx, __shfl_xor_sync(0xffffffffu, mx, 2));
            float mold = mS[row];
            float mnew = fmaxf(mold, mx);
            float fct = __expf(mold - mnew);
            float rs = 0.f;
#pragma unroll
            for (int j = 0; j < 16; ++j) { p[j] = __expf(p[j] - mnew); rs += p[j]; }
            rs += __shfl_xor_sync(0xffffffffu, rs, 1);
            rs += __shfl_xor_sync(0xffffffffu, rs, 2);
            if ((lane & 3) == 0) {
                mS[row] = mnew;
                lS[row] = lS[row] * fct + rs;
                fS[row] = fct;
            }
#pragma unroll
            for (int ni = 0; ni < 8; ++ni) {
                float v0 = p[ni * 2], v1 = p[ni * 2 + 1];
                __nv_bfloat16 h0 = __float2bfloat16(v0), h1 = __float2bfloat16(v1);
                __nv_bfloat16 l0 = __float2bfloat16(v0 - __bfloat162float(h0));
                __nv_bfloat16 l1 = __float2bfloat16(v1 - __bfloat162float(h1));
                int kl = ni * 8 + ccol;
                *(uint32_t*)(sm + APH + row * 144 + kl * 2) = pack2(h0, h1);
                *(uint32_t*)(sm + APL + row * 144 + kl * 2) = pack2(l0, l1);
                // sheared Pd: column r = kl - row + 63; complement slot zeroed
                __nv_bfloat16 hs[2] = {h0, h1}, ls[2] = {l0, l1};
#pragma unroll
                for (int c = 0; c < 2; ++c) {
                    int r = kl + c - row + 63;          // 0..126
                    *(uint16_t*)(sm + APDH + row * 272 + r * 2) = bf16bits(hs[c]);
                    *(uint16_t*)(sm + APDL + row * 272 + r * 2) = bf16bits(ls[c]);
                    int rz = (r + 64) & 127;
                    *(uint16_t*)(sm + APDH + row * 272 + rz * 2) = 0;
                    *(uint16_t*)(sm + APDL + row * 272 + rz * 2) = 0;
                }
            }
        }
        __syncthreads();

        // rescale accumulator
        {
            float f0 = fS[crow], f1 = fS[crow + 8];
#pragma unroll
            for (int ni = 0; ni < 8; ++ni) {
                acc[ni][0] *= f0; acc[ni][1] *= f0;
                acc[ni][2] *= f1; acc[ni][3] *= f1;
            }
        }

        // ---- O += P·V  (contraction over k) ----
#pragma unroll
        for (int k16 = 0; k16 < 64; k16 += 16) {
            uint32_t ph[4], pl[4];
            LDSM4(ph[0], ph[1], ph[2], ph[3],
                  smb + APH + (w * 16 + frow) * 144 + (k16 + fcolb) * 2);
            LDSM4(pl[0], pl[1], pl[2], pl[3],
                  smb + APL + (w * 16 + frow) * 144 + (k16 + fcolb) * 2);
#pragma unroll
            for (int ng = 0; ng < 4; ++ng) {
                uint32_t vh4[4], vl4[4];
                LDSM4T(vh4[0], vh4[1], vh4[2], vh4[3],
                       smb + AVH + (k16 + frow) * 144 + (ng * 16 + fcolb) * 2);
                LDSM4T(vl4[0], vl4[1], vl4[2], vl4[3],
                       smb + AVL + (k16 + frow) * 144 + (ng * 16 + fcolb) * 2);
                uint32_t f0h[2] = {vh4[0], vh4[1]}, f1h[2] = {vh4[2], vh4[3]};
                uint32_t f0l[2] = {vl4[0], vl4[1]}, f1l[2] = {vl4[2], vl4[3]};
                MMA_OP(acc[2 * ng],     ph, f0h);
                MMA_OP(acc[2 * ng],     ph, f0l);
                MMA_OP(acc[2 * ng],     pl, f0h);
                MMA_OP(acc[2 * ng + 1], ph, f1h);
                MMA_OP(acc[2 * ng + 1], ph, f1l);
                MMA_OP(acc[2 * ng + 1], pl, f1h);
            }
        }
        // ---- O += Pd·Ev (contraction over r, 128) ----
#pragma unroll
        for (int r16 = 0; r16 < 128; r16 += 16) {
            uint32_t ph[4], pl[4];
            LDSM4(ph[0], ph[1], ph[2], ph[3],
                  smb + APDH + (w * 16 + frow) * 272 + (r16 + fcolb) * 2);
            LDSM4(pl[0], pl[1], pl[2], pl[3],
                  smb + APDL + (w * 16 + frow) * 272 + (r16 + fcolb) * 2);
#pragma unroll
            for (int ng = 0; ng < 4; ++ng) {
                uint32_t eh4[4], el4[4];
                LDSM4T(eh4[0], eh4[1], eh4[2], eh4[3],
                       smb + AEVH + (r16 + frow) * 144 + (ng * 16 + fcolb) * 2);
                LDSM4T(el4[0], el4[1], el4[2], el4[3],
                       smb + AEVL + (r16 + frow) * 144 + (ng * 16 + fcolb) * 2);
                uint32_t f0h[2] = {eh4[0], eh4[1]}, f1h[2] = {eh4[2], eh4[3]};
                uint32_t f0l[2] = {el4[0], el4[1]}, f1l[2] = {el4[2], el4[3]};
                MMA_OP(acc[2 * ng],     ph, f0h);
                MMA_OP(acc[2 * ng],     ph, f0l);
                MMA_OP(acc[2 * ng],     pl, f0h);
                MMA_OP(acc[2 * ng + 1], ph, f1h);
                MMA_OP(acc[2 * ng + 1], ph, f1l);
                MMA_OP(acc[2 * ng + 1], pl, f1h);
            }
        }
    }

    // epilogue: normalize by l, emit bf16 hi/lo
    float inv0 = 1.f / lS[crow];
    float inv1 = 1.f / lS[crow + 8];
    __nv_bfloat16* Ogh = Oh + (size_t)(b * LL + q0) * DD + h * HD;
    __nv_bfloat16* Ogl = Ol + (size_t)(b * LL + q0) * DD + h * HD;
#pragma unroll
    for (int ni = 0; ni < 8; ++ni) {
#pragma unroll
        for (int hf = 0; hf < 2; ++hf) {
            float v0 = acc[ni][hf * 2]     * (hf ? inv1 : inv0);
            float v1 = acc[ni][hf * 2 + 1] * (hf ? inv1 : inv0);
            __nv_bfloat16 h0 = __float2bfloat16(v0), h1 = __float2bfloat16(v1);
            __nv_bfloat16 l0 = __float2bfloat16(v0 - __bfloat162float(h0));
            __nv_bfloat16 l1 = __float2bfloat16(v1 - __bfloat162float(h1));
            size_t off = (size_t)(crow + hf * 8) * DD + ni * 8 + ccol;
            *(uint32_t*)&Ogh[off] = pack2(h0, h1);
            *(uint32_t*)&Ogl[off] = pack2(l0, l1);
        }
    }
}

// ---------------------------------------------------------------------------
// Launch
// ---------------------------------------------------------------------------
extern "C" void kernel_launch(void* const* d_in, const int* in_sizes, int n_in,
                              void* d_out, int out_size) {
    const float* x   = (const float*)d_in[0];
    const float* Wq  = (const float*)d_in[1];
    const float* Wk  = (const float*)d_in[2];
    const float* Wv  = (const float*)d_in[3];
    const float* Wo  = (const float*)d_in[4];
    const float* pek = (const float*)d_in[5];
    const float* pev = (const float*)d_in[6];
    float* out = (float*)d_out;

    __nv_bfloat16 *xh, *xl, *wh, *wl, *Qh, *Ql, *Kh, *Kl, *Vh, *Vl, *Oh, *Ol;
    __nv_bfloat16 *pekh, *pekl, *pevh, *pevl;
    cudaGetSymbolAddress((void**)&xh, g_xh);
    cudaGetSymbolAddress((void**)&xl, g_xl);
    cudaGetSymbolAddress((void**)&wh, g_wh);
    cudaGetSymbolAddress((void**)&wl, g_wl);
    cudaGetSymbolAddress((void**)&Qh, g_Qh);
    cudaGetSymbolAddress((void**)&Ql, g_Ql);
    cudaGetSymbolAddress((void**)&Kh, g_Kh);
    cudaGetSymbolAddress((void**)&Kl, g_Kl);
    cudaGetSymbolAddress((void**)&Vh, g_Vh);
    cudaGetSymbolAddress((void**)&Vl, g_Vl);
    cudaGetSymbolAddress((void**)&Oh, g_Oh);
    cudaGetSymbolAddress((void**)&Ol, g_Ol);
    cudaGetSymbolAddress((void**)&pekh, g_pekh);
    cudaGetSymbolAddress((void**)&pekl, g_pekl);
    cudaGetSymbolAddress((void**)&pevh, g_pevh);
    cudaGetSymbolAddress((void**)&pevl, g_pevl);

    cudaFuncSetAttribute(gemm_mma, cudaFuncAttributeMaxDynamicSharedMemorySize, GEMM_SMEM);
    cudaFuncSetAttribute(attn_fused, cudaFuncAttributeMaxDynamicSharedMemorySize, ATTN_SMEM);

    const int n4x = MROWS * DD / 4;
    const int n4w = DD * DD / 4;
    const int n4p = PEN * HD / 4;
    dim3 ggemm(DD / 128, MROWS / 128);

    split_kernel<<<(n4x + 255) / 256, 256>>>(x, xh, xl, n4x);

    split_kernel<<<(n4w + 255) / 256, 256>>>(Wq, wh, wl, n4w);
    gemm_mma<<<ggemm, 256, GEMM_SMEM>>>(xh, xl, wh, wl, nullptr, Qh, Ql);
    split_kernel<<<(n4w + 255) / 256, 256>>>(Wk, wh, wl, n4w);
    gemm_mma<<<ggemm, 256, GEMM_SMEM>>>(xh, xl, wh, wl, nullptr, Kh, Kl);
    split_kernel<<<(n4w + 255) / 256, 256>>>(Wv, wh, wl, n4w);
    gemm_mma<<<ggemm, 256, GEMM_SMEM>>>(xh, xl, wh, wl, nullptr, Vh, Vl);

    split_kernel<<<(n4p + 255) / 256, 256>>>(pek, pekh, pekl, n4p);
    split_kernel<<<(n4p + 255) / 256, 256>>>(pev, pevh, pevl, n4p);

    attn_fused<<<dim3(16, 64), 128, ATTN_SMEM>>>(Qh, Ql, Kh, Kl, Vh, Vl,
                                                 pekh, pekl, pevh, pevl, Oh, Ol);

    split_kernel<<<(n4w + 255) / 256, 256>>>(Wo, wh, wl, n4w);
    gemm_mma<<<ggemm, 256, GEMM_SMEM>>>(Oh, Ol, wh, wl, out, nullptr, nullptr);
}